// round 15
// baseline (speedup 1.0000x reference)
#include <cuda_runtime.h>
#include <cstdint>

// Fixed shapes
#define TT 1024
#define BB 8
#define HH 8
#define NN 32
#define DEPTH 4
#define ROWP 36                 // padded row stride (144B): 16B-aligned
#define SLOT (NN * ROWP)
#define SLOTB (SLOT * 4)

__device__ __forceinline__ void cp16(uint32_t d, const void* s) {
    asm volatile("cp.async.cg.shared.global [%0], [%1], 16;\n" :: "r"(d), "l"(s) : "memory");
}
__device__ __forceinline__ void cpcommit() {
    asm volatile("cp.async.commit_group;\n" ::: "memory");
}
template<int N> __device__ __forceinline__ void cpwait() {
    asm volatile("cp.async.wait_group %0;\n" :: "n"(N) : "memory");
}
__device__ __forceinline__ float ex2f(float x) { float y; asm("ex2.approx.f32 %0, %1;" : "=f"(y) : "f"(x)); return y; }
__device__ __forceinline__ float rcpf(float x) { float y; asm("rcp.approx.f32 %0, %1;" : "=f"(y) : "f"(x)); return y; }
__device__ __forceinline__ float sqrtaf(float x){ float y; asm("sqrt.approx.f32 %0, %1;" : "=f"(y) : "f"(x)); return y; }

// tanh(y) = 2/(1+exp(-2y)) - 1 ; exp(-2y) = ex2(C2*y). Limit-safe for all y.
#define C2   (-2.8853900817779268f)   // -2*log2(e)
#define L2E  (1.4426950408889634f)
#define INV32   0.03125f
#define INV1024 0.0009765625f

__global__ __launch_bounds__(256, 1)
void e86_cell_kernel(const float* __restrict__ x,
                     const float* __restrict__ S0,
                     const float* __restrict__ scale_p,
                     const float* __restrict__ bias_p,
                     float* __restrict__ out,
                     int write_sfinal)
{
    __shared__ __align__(16) float ring[DEPTH * SLOT];
    __shared__ float rpart[2][8][NN];   // retrieved partials, parity t&1
    __shared__ float qpart[2][8][NN];   // Sq partials,        parity t&1
    __shared__ float vpart[4][4][NN];   // v partials, ring slot s&3 (written 2 ahead)
    __shared__ float knarr[2][NN];      // normalized key, parity s&1 (written 2 ahead)
    __shared__ float betas[2];          // beta, parity s&1

    const int tid  = threadIdx.x;
    const int w    = tid >> 5;       // warp 0..7 owns S COLUMNS [4w, 4w+4)
    const int lane = tid & 31;       // lane = ROW index i
    const int g    = w >> 2;         // prep group: 0 preps even steps, 1 odd steps
    const int head = blockIdx.x;

    const float scale = scale_p[0];
    const float bias  = bias_p[0];

    const float* xh = x + (size_t)head * (NN * NN);
    const size_t xs = (size_t)(BB * HH * NN * NN);   // 65536 floats per timestep

    // S[j] = S[lane][4w+j]
    float S[4];
    {
        const float* p = S0 + (size_t)head * (NN * NN) + (size_t)lane * NN + 4 * w;
        #pragma unroll
        for (int j = 0; j < 4; j++) S[j] = p[j];
    }

    // cp.async: 256 16B chunks per tile, ONE per thread
    const uint32_t sring = (uint32_t)__cvta_generic_to_shared(ring);
    const uint32_t so = (uint32_t)((tid >> 3) * (ROWP * 4) + (tid & 7) * 16);
    const float* gsrc = xh + (tid >> 3) * NN + (tid & 7) * 4;

    // ---- prologue: fill ring with tiles 0..3 ----
    #pragma unroll
    for (int s = 0; s < DEPTH; s++) {
        cp16(sring + s * SLOTB + so, gsrc + (size_t)s * xs);
        cpcommit();
    }
    cpwait<2>();            // tiles 0,1: this thread's chunk done
    __syncthreads();        // all chunks of tiles 0,1 visible

    // prep(s): group (s&1) warps only. From tile s&3: knarr[s&1], betas[s&1],
    // vpart[s&3][w&3]. Tile-only; no recurrence dependencies.
    auto prep = [&](int s) {
        const float* T = ring + (s & 3) * SLOT;
        // rowsum of lane's own row (redundant across the 4 group warps)
        const float4* r4 = (const float4*)(T + lane * ROWP);
        float a0 = 0.f, a1 = 0.f, a2 = 0.f, a3 = 0.f;
        #pragma unroll
        for (int c = 0; c < 8; c += 4) {
            float4 q0 = r4[c + 0], q1 = r4[c + 1], q2 = r4[c + 2], q3 = r4[c + 3];
            a0 += (q0.x + q0.y) + (q0.z + q0.w);
            a1 += (q1.x + q1.y) + (q1.z + q1.w);
            a2 += (q2.x + q2.y) + (q2.z + q2.w);
            a3 += (q3.x + q3.y) + (q3.z + q3.w);
        }
        float rowsum = (a0 + a1) + (a2 + a3);
        float klm = rowsum * INV32;                 // k[lane]
        // v partial first (independent of ladder): rows 8(w&3).. of column lane
        const float* cb = T + (8 * (w & 3)) * ROWP + lane;
        float vp = ((cb[0] + cb[ROWP]) + (cb[2 * ROWP] + cb[3 * ROWP]))
                 + ((cb[4 * ROWP] + cb[5 * ROWP]) + (cb[6 * ROWP] + cb[7 * ROWP]));
        vpart[s & 3][w & 3][lane] = vp;
        // norm + beta ladder; only the group's lead warp (w%4==0) publishes
        if ((w & 3) == 0) {
            float s1 = rowsum, s2 = klm * klm;
            #pragma unroll
            for (int o = 16; o; o >>= 1) {
                s1 += __shfl_xor_sync(0xffffffffu, s1, o);
                s2 += __shfl_xor_sync(0xffffffffu, s2, o);
            }
            float rn = rcpf(sqrtaf(s2) + 1e-6f);
            knarr[s & 1][lane] = klm * rn;
            if (lane == 0)
                betas[s & 1] = rcpf(1.0f + ex2f(-L2E * fmaf(scale, s1 * INV1024, bias)));
        }
    };

    if (g == 0) prep(0);
    else        prep(1);
    __syncthreads();        // knarr/betas/vpart for steps 0,1 visible

    // kn/beta for the CURRENT step, in registers (loaded one iter ahead)
    float kn[4], beta;
    {
        const float* ka = knarr[0];
        #pragma unroll
        for (int j = 0; j < 4; j++) kn[j] = ka[4 * w + j];
        beta = betas[0];
    }

    // ---- main scan: ONE block barrier per step ----
    for (int t = 0; t < TT; t++) {
        const int p  = t & 1;
        const int pn = p ^ 1;

        // [chain] retrieved partial over this warp's 4 columns
        {
            float r = S[0] * kn[0];
            r = fmaf(S[1], kn[1], r);
            r = fmaf(S[2], kn[2], r);
            r = fmaf(S[3], kn[3], r);
            rpart[p][w][lane] = r;
        }

        cpwait<1>();          // tile t+2 resident (this thread's chunk)
        __syncthreads();      // BAR(t)

        // refill slot t&3 with tile t+4 (its last read: prep(t) @ iter t-2)
        if (t + 4 < TT) {
            cp16(sring + (uint32_t)(t & 3) * SLOTB + so, gsrc + (size_t)(t + 4) * xs);
        }
        cpcommit();           // exactly one group per iteration

        // [fill] output for step t-1: warp w writes rows 4w..4w+3 (lane<4)
        if (t >= 1 && lane < 4) {
            const int row = 4 * w + lane;
            float q = ((qpart[pn][0][row] + qpart[pn][1][row])
                    +  (qpart[pn][2][row] + qpart[pn][3][row]))
                    + ((qpart[pn][4][row] + qpart[pn][5][row])
                    +  (qpart[pn][6][row] + qpart[pn][7][row]));
            float sg = rcpf(1.0f + ex2f(-L2E * q));
            out[(size_t)(t - 1) * (BB * HH * NN) + (size_t)head * NN + row] = q * q * sg;
        }

        // [chain] combine -> delta; tanh -> S_new
        {
            float ret = ((rpart[p][0][lane] + rpart[p][1][lane])
                      +  (rpart[p][2][lane] + rpart[p][3][lane]))
                      + ((rpart[p][4][lane] + rpart[p][5][lane])
                      +  (rpart[p][6][lane] + rpart[p][7][lane]));
            const float (*vp)[NN] = vpart[t & 3];
            float vv  = ((vp[0][lane] + vp[1][lane]) + (vp[2][lane] + vp[3][lane])) * INV32;
            float delta = vv - ret;
            float b2 = C2 * beta, d2 = C2 * delta;
            #pragma unroll
            for (int j = 0; j < 4; j++) {
                float z = fmaf(b2, S[j], d2 * kn[j]);
                S[j] = fmaf(2.0f, rcpf(1.0f + ex2f(z)), -1.0f);
            }
        }

        // [fill] Sq partial for step t
        {
            float q = S[0] * kn[0];
            q = fmaf(S[1], kn[1], q);
            q = fmaf(S[2], kn[2], q);
            q = fmaf(S[3], kn[3], q);
            qpart[p][w][lane] = q;
        }

        // [fill] prep step t+2 (my group's parity); tile t+2 visible since BAR(t)
        if (t + 2 < TT && g == p) prep(t + 2);

        // [fill] load kn/beta for step t+1 (published at iter t-1, pre-BAR(t))
        if (t + 1 < TT) {
            const float* ka = knarr[pn];
            #pragma unroll
            for (int j = 0; j < 4; j++) kn[j] = ka[4 * w + j];
            beta = betas[pn];
        }
    }

    // tail: output for step TT-1, optional S_final
    __syncthreads();
    {
        const int pl = (TT - 1) & 1;
        if (lane < 4) {
            const int row = 4 * w + lane;
            float q = ((qpart[pl][0][row] + qpart[pl][1][row])
                    +  (qpart[pl][2][row] + qpart[pl][3][row]))
                    + ((qpart[pl][4][row] + qpart[pl][5][row])
                    +  (qpart[pl][6][row] + qpart[pl][7][row]));
            float sg = rcpf(1.0f + ex2f(-L2E * q));
            out[(size_t)(TT - 1) * (BB * HH * NN) + (size_t)head * NN + row] = q * q * sg;
        }
    }
    if (write_sfinal) {
        float* dst = out + (size_t)TT * (BB * HH * NN)
                   + (size_t)head * (NN * NN) + (size_t)lane * NN + 4 * w;
        #pragma unroll
        for (int j = 0; j < 4; j++) dst[j] = S[j];
    }
}

extern "C" void kernel_launch(void* const* d_in, const int* in_sizes, int n_in,
                              void* d_out, int out_size)
{
    const float* x       = (const float*)d_in[0];
    const float* S0      = (const float*)d_in[1];
    const float* scale_p = (const float*)d_in[2];
    const float* bias_p  = (const float*)d_in[3];
    float* out = (float*)d_out;

    const int out_main = TT * BB * HH * NN;              // 2,097,152
    const int out_full = out_main + BB * HH * NN * NN;   // 2,162,688
    const int write_sfinal = (out_size >= out_full) ? 1 : 0;

    e86_cell_kernel<<<BB * HH, 256>>>(x, S0, scale_p, bias_p, out, write_sfinal);
}

// round 16
// speedup vs baseline: 1.7147x; 1.7147x over previous
#include <cuda_runtime.h>
#include <cstdint>

// Fixed shapes
#define TT 1024
#define BB 8
#define HH 8
#define NN 32
#define NHEAD 64
#define ROWP 36                 // padded row stride (floats) for phase-1 smem tiles
#define SLOT (NN * ROWP)

// Param record per (t, head): kn[32], v[32], beta, pad -> 72 floats (288B, 16B-mult)
#define PSLOT 72
#define PDEPTH 8

__device__ __align__(16) float g_param[(size_t)TT * NHEAD * PSLOT];

__device__ __forceinline__ void cp16(uint32_t d, const void* s) {
    asm volatile("cp.async.cg.shared.global [%0], [%1], 16;\n" :: "r"(d), "l"(s) : "memory");
}
__device__ __forceinline__ void cpcommit() {
    asm volatile("cp.async.commit_group;\n" ::: "memory");
}
template<int N> __device__ __forceinline__ void cpwait() {
    asm volatile("cp.async.wait_group %0;\n" :: "n"(N) : "memory");
}
__device__ __forceinline__ float ex2f(float x) { float y; asm("ex2.approx.f32 %0, %1;" : "=f"(y) : "f"(x)); return y; }
__device__ __forceinline__ float rcpf(float x) { float y; asm("rcp.approx.f32 %0, %1;" : "=f"(y) : "f"(x)); return y; }
__device__ __forceinline__ float sqrtaf(float x){ float y; asm("sqrt.approx.f32 %0, %1;" : "=f"(y) : "f"(x)); return y; }

// tanh(y) = 2/(1+exp(-2y)) - 1 ; exp(-2y) = ex2(C2*y). Limit-safe for all y.
#define C2   (-2.8853900817779268f)   // -2*log2(e)
#define L2E  (1.4426950408889634f)
#define INV32   0.03125f
#define INV1024 0.0009765625f

// ============================================================================
// Phase 1: per-tile reductions (kn, v, beta) -> g_param. Fully parallel.
// One warp per tile; 4 warps/CTA; grid-stride over 65536 tiles.
// ============================================================================
__global__ __launch_bounds__(128)
void e86_phase1(const float* __restrict__ x,
                const float* __restrict__ scale_p,
                const float* __restrict__ bias_p)
{
    __shared__ __align__(16) float tl[4][SLOT];

    const int w    = threadIdx.x >> 5;
    const int lane = threadIdx.x & 31;
    const float scale = scale_p[0];
    const float bias  = bias_p[0];

    const int stride = gridDim.x * 4;
    for (int tau = blockIdx.x * 4 + w; tau < TT * NHEAD; tau += stride) {
        const int t = tau >> 6, head = tau & 63;
        const float4* src = (const float4*)(x + (size_t)t * (NHEAD * NN * NN)
                                              + (size_t)head * (NN * NN) + lane * NN);
        float4 r[8];
        #pragma unroll
        for (int c = 0; c < 8; c++) r[c] = src[c];

        // stage rows in smem for the column sums
        float4* Trow = (float4*)(tl[w] + lane * ROWP);
        #pragma unroll
        for (int c = 0; c < 8; c++) Trow[c] = r[c];

        // rowsum (k) for lane's own row
        float a0 = 0.f, a1 = 0.f, a2 = 0.f, a3 = 0.f;
        #pragma unroll
        for (int c = 0; c < 8; c += 4) {
            a0 += (r[c+0].x + r[c+0].y) + (r[c+0].z + r[c+0].w);
            a1 += (r[c+1].x + r[c+1].y) + (r[c+1].z + r[c+1].w);
            a2 += (r[c+2].x + r[c+2].y) + (r[c+2].z + r[c+2].w);
            a3 += (r[c+3].x + r[c+3].y) + (r[c+3].z + r[c+3].w);
        }
        float rowsum = (a0 + a1) + (a2 + a3);
        float klm = rowsum * INV32;

        float s1 = rowsum, s2 = klm * klm;
        #pragma unroll
        for (int o = 16; o; o >>= 1) {
            s1 += __shfl_xor_sync(0xffffffffu, s1, o);
            s2 += __shfl_xor_sync(0xffffffffu, s2, o);
        }
        float rn   = rcpf(sqrtaf(s2) + 1e-6f);
        float beta = rcpf(1.0f + ex2f(-L2E * fmaf(scale, s1 * INV1024, bias)));

        __syncwarp();   // all rows staged before column reads

        // column sum for column `lane` (bank-conflict-free: stride ROWP=36)
        const float* cb = tl[w] + lane;
        float v0 = 0.f, v1 = 0.f, v2 = 0.f, v3 = 0.f;
        #pragma unroll
        for (int rr = 0; rr < NN; rr += 4) {
            v0 += cb[(rr + 0) * ROWP];
            v1 += cb[(rr + 1) * ROWP];
            v2 += cb[(rr + 2) * ROWP];
            v3 += cb[(rr + 3) * ROWP];
        }
        float vsum = (v0 + v1) + (v2 + v3);

        float* P = g_param + (size_t)tau * PSLOT;
        P[lane]      = klm * rn;        // kn
        P[NN + lane] = vsum * INV32;    // v (pre-divided)
        if (lane == 0) P[2 * NN] = beta;

        __syncwarp();   // column reads done before next tile overwrites smem
    }
}

// ============================================================================
// Phase 2: the sequential scan. 64 CTAs x 128 threads; warp w owns S columns
// [8w, 8w+8), lane = row. Params streamed from g_param via cp.async ring.
// ============================================================================
__global__ __launch_bounds__(128, 1)
void e86_phase2(const float* __restrict__ S0,
                float* __restrict__ out,
                int write_sfinal)
{
    __shared__ __align__(16) float pring[PDEPTH * PSLOT];
    __shared__ float rpart[2][4][NN + 1];   // +1 pad: kill 4-way bank conflict
    __shared__ float qpart[2][4][NN + 1];

    const int tid  = threadIdx.x;
    const int w    = tid >> 5;
    const int lane = tid & 31;
    const int head = blockIdx.x;

    // S[j] = S[lane][8w+j]
    float S[8];
    {
        const float* p = S0 + (size_t)head * (NN * NN) + (size_t)lane * NN + 8 * w;
        #pragma unroll
        for (int j = 0; j < 8; j++) S[j] = p[j];
    }

    const float* psrc = g_param + (size_t)head * PSLOT;   // step t at + t*NHEAD*PSLOT
    const size_t pstride = (size_t)NHEAD * PSLOT;
    const uint32_t spr = (uint32_t)__cvta_generic_to_shared(pring);

    // ---- prologue: 8 param groups (steps 0..7), 18 x 16B chunks each ----
    #pragma unroll
    for (int s = 0; s < PDEPTH; s++) {
        if (tid < 18) cp16(spr + (uint32_t)(s * PSLOT * 4 + tid * 16),
                           psrc + (size_t)s * pstride + tid * 4);
        cpcommit();
    }
    cpwait<6>();            // steps 0,1 retired (copying threads)
    __syncthreads();        // visible to all

    // params for the CURRENT step, in registers
    float kn[8], vv, beta;
    {
        const float* ps = pring;
        #pragma unroll
        for (int j = 0; j < 8; j++) kn[j] = ps[8 * w + j];
        vv   = ps[NN + lane];
        beta = ps[2 * NN];
    }

    // ---- main scan: one barrier per step, no ladders, no prep ----
    for (int t = 0; t < TT; t++) {
        const int p  = t & 1;
        const int pn = p ^ 1;

        // [chain] retrieved partial (this warp's 8 columns)
        {
            float r0 = S[0] * kn[0], r1 = S[1] * kn[1];
            float r2 = S[2] * kn[2], r3 = S[3] * kn[3];
            r0 = fmaf(S[4], kn[4], r0); r1 = fmaf(S[5], kn[5], r1);
            r2 = fmaf(S[6], kn[6], r2); r3 = fmaf(S[7], kn[7], r3);
            rpart[p][w][lane] = (r0 + r1) + (r2 + r3);
        }

        cpwait<6>();        // groups <= t+1 retired => params t+1 resident
        __syncthreads();    // BAR(t): rpart[p], qpart[pn], param copies visible

        // refill slot t&7 with step t+8 (slot's last read: params t, end iter t-1)
        if (tid < 18 && t + PDEPTH < TT)
            cp16(spr + (uint32_t)((t & 7) * PSLOT * 4 + tid * 16),
                 psrc + (size_t)(t + PDEPTH) * pstride + tid * 4);
        cpcommit();         // exactly one group per iteration

        // [fill] output for step t-1: warp w writes rows 8w..8w+7
        if (t >= 1 && lane < 8) {
            const int row = 8 * w + lane;
            float q = (qpart[pn][0][row] + qpart[pn][1][row])
                    + (qpart[pn][2][row] + qpart[pn][3][row]);
            float sg = rcpf(1.0f + ex2f(-L2E * q));
            out[(size_t)(t - 1) * (BB * HH * NN) + (size_t)head * NN + row] = q * q * sg;
        }

        // [chain] combine -> delta; tanh -> S_new
        {
            float ret = (rpart[p][0][lane] + rpart[p][1][lane])
                      + (rpart[p][2][lane] + rpart[p][3][lane]);
            float delta = vv - ret;
            float b2 = C2 * beta, d2 = C2 * delta;
            #pragma unroll
            for (int j = 0; j < 8; j++) {
                float z = fmaf(b2, S[j], d2 * kn[j]);
                S[j] = fmaf(2.0f, rcpf(1.0f + ex2f(z)), -1.0f);
            }
        }

        // [fill] Sq partial for step t
        {
            float q0 = S[0] * kn[0], q1 = S[1] * kn[1];
            float q2 = S[2] * kn[2], q3 = S[3] * kn[3];
            q0 = fmaf(S[4], kn[4], q0); q1 = fmaf(S[5], kn[5], q1);
            q2 = fmaf(S[6], kn[6], q2); q3 = fmaf(S[7], kn[7], q3);
            qpart[p][w][lane] = (q0 + q1) + (q2 + q3);
        }

        // [fill] load params for step t+1 (resident + visible since BAR(t))
        if (t + 1 < TT) {
            const float* ps = pring + ((t + 1) & 7) * PSLOT;
            #pragma unroll
            for (int j = 0; j < 8; j++) kn[j] = ps[8 * w + j];
            vv   = ps[NN + lane];
            beta = ps[2 * NN];
        }
    }

    // tail: output for step TT-1, optional S_final
    __syncthreads();
    {
        const int pl = (TT - 1) & 1;
        if (lane < 8) {
            const int row = 8 * w + lane;
            float q = (qpart[pl][0][row] + qpart[pl][1][row])
                    + (qpart[pl][2][row] + qpart[pl][3][row]);
            float sg = rcpf(1.0f + ex2f(-L2E * q));
            out[(size_t)(TT - 1) * (BB * HH * NN) + (size_t)head * NN + row] = q * q * sg;
        }
    }
    if (write_sfinal) {
        float* dst = out + (size_t)TT * (BB * HH * NN)
                   + (size_t)head * (NN * NN) + (size_t)lane * NN + 8 * w;
        #pragma unroll
        for (int j = 0; j < 8; j++) dst[j] = S[j];
    }
}

extern "C" void kernel_launch(void* const* d_in, const int* in_sizes, int n_in,
                              void* d_out, int out_size)
{
    const float* x       = (const float*)d_in[0];
    const float* S0      = (const float*)d_in[1];
    const float* scale_p = (const float*)d_in[2];
    const float* bias_p  = (const float*)d_in[3];
    float* out = (float*)d_out;

    const int out_main = TT * BB * HH * NN;              // 2,097,152
    const int out_full = out_main + BB * HH * NN * NN;   // 2,162,688
    const int write_sfinal = (out_size >= out_full) ? 1 : 0;

    e86_phase1<<<1024, 128>>>(x, scale_p, bias_p);
    e86_phase2<<<NHEAD, 128>>>(S0, out, write_sfinal);
}

// round 17
// speedup vs baseline: 2.0054x; 1.1696x over previous
#include <cuda_runtime.h>
#include <cstdint>

// Fixed shapes
#define TT 1024
#define BB 8
#define HH 8
#define NN 32
#define NHEAD 64
#define ROWP 36                 // padded row stride (floats), conflict-free
#define SLOT (NN * ROWP)        // 1152 floats per tile buffer

// Param record per (t, head): kn[32], v[32], beta, pad -> 72 floats (288B)
#define PSLOT 72
#define PDEPTH 8

__device__ __align__(16) float g_param[(size_t)TT * NHEAD * PSLOT];

__device__ __forceinline__ void cp16(uint32_t d, const void* s) {
    asm volatile("cp.async.cg.shared.global [%0], [%1], 16;\n" :: "r"(d), "l"(s) : "memory");
}
__device__ __forceinline__ void cpcommit() {
    asm volatile("cp.async.commit_group;\n" ::: "memory");
}
template<int N> __device__ __forceinline__ void cpwait() {
    asm volatile("cp.async.wait_group %0;\n" :: "n"(N) : "memory");
}
__device__ __forceinline__ float ex2f(float x) { float y; asm("ex2.approx.f32 %0, %1;" : "=f"(y) : "f"(x)); return y; }
__device__ __forceinline__ float rcpf(float x) { float y; asm("rcp.approx.f32 %0, %1;" : "=f"(y) : "f"(x)); return y; }
__device__ __forceinline__ float sqrtaf(float x){ float y; asm("sqrt.approx.f32 %0, %1;" : "=f"(y) : "f"(x)); return y; }

// tanh(y) = 2/(1+exp(-2y)) - 1 ; exp(-2y) = ex2(C2*y). Limit-safe for all y.
#define C2   (-2.8853900817779268f)   // -2*log2(e)
#define L2E  (1.4426950408889634f)
#define INV32   0.03125f
#define INV1024 0.0009765625f

// ============================================================================
// Phase 1: per-tile reductions (kn, v, beta) -> g_param.
// One warp per tile, cp.async double-buffered; grid 888 CTAs x 4 warps.
// ============================================================================
__global__ __launch_bounds__(128)
void e86_phase1(const float* __restrict__ x,
                const float* __restrict__ scale_p,
                const float* __restrict__ bias_p)
{
    __shared__ __align__(16) float tl[4][2][SLOT];

    const int w    = threadIdx.x >> 5;
    const int lane = threadIdx.x & 31;
    const float scale = scale_p[0];
    const float bias  = bias_p[0];

    const int gw = blockIdx.x * 4 + w;      // global warp id
    const int nw = gridDim.x * 4;           // total warps
    const int row8 = lane >> 3, c8 = lane & 7;

    const uint32_t sb[2] = {
        (uint32_t)__cvta_generic_to_shared(&tl[w][0][0]),
        (uint32_t)__cvta_generic_to_shared(&tl[w][1][0])
    };

    // prefetch(tau -> buffer b): 8 sweeps x 32 lanes x 16B = 4KB tile
    auto prefetch = [&](int tau, uint32_t b) {
        const float* g = x + (size_t)tau * (NN * NN) + row8 * NN + c8 * 4;
        uint32_t d = b + (uint32_t)(row8 * ROWP + c8 * 4) * 4;
        #pragma unroll
        for (int s = 0; s < 8; s++)
            cp16(d + s * (4 * ROWP * 4), g + s * (4 * NN));
        cpcommit();
    };

    int tau = gw;
    if (tau < TT * NHEAD) prefetch(tau, sb[0]); else cpcommit();

    int i = 0;
    for (; tau < TT * NHEAD; tau += nw, i++) {
        const int nxt = tau + nw;
        if (nxt < TT * NHEAD) prefetch(nxt, sb[(i + 1) & 1]);
        else cpcommit();

        cpwait<1>();        // tile i resident (this lane's chunks)
        __syncwarp();       // all lanes' chunks visible

        const float* T = tl[w][i & 1];

        // rowsum of lane's own row (8x LDS.128, conflict-free)
        const float4* r4 = (const float4*)(T + lane * ROWP);
        float a0 = 0.f, a1 = 0.f, a2 = 0.f, a3 = 0.f;
        #pragma unroll
        for (int c = 0; c < 8; c += 4) {
            float4 q0 = r4[c + 0], q1 = r4[c + 1], q2 = r4[c + 2], q3 = r4[c + 3];
            a0 += (q0.x + q0.y) + (q0.z + q0.w);
            a1 += (q1.x + q1.y) + (q1.z + q1.w);
            a2 += (q2.x + q2.y) + (q2.z + q2.w);
            a3 += (q3.x + q3.y) + (q3.z + q3.w);
        }
        float rowsum = (a0 + a1) + (a2 + a3);
        float klm = rowsum * INV32;

        // column sum for column `lane` (stride ROWP: conflict-free)
        const float* cb = T + lane;
        float v0 = 0.f, v1 = 0.f, v2 = 0.f, v3 = 0.f;
        #pragma unroll
        for (int rr = 0; rr < NN; rr += 4) {
            v0 += cb[(rr + 0) * ROWP];
            v1 += cb[(rr + 1) * ROWP];
            v2 += cb[(rr + 2) * ROWP];
            v3 += cb[(rr + 3) * ROWP];
        }
        float vsum = (v0 + v1) + (v2 + v3);

        float s1 = rowsum, s2 = klm * klm;
        #pragma unroll
        for (int o = 16; o; o >>= 1) {
            s1 += __shfl_xor_sync(0xffffffffu, s1, o);
            s2 += __shfl_xor_sync(0xffffffffu, s2, o);
        }
        float rn   = rcpf(sqrtaf(s2) + 1e-6f);
        float beta = rcpf(1.0f + ex2f(-L2E * fmaf(scale, s1 * INV1024, bias)));

        float* P = g_param + (size_t)tau * PSLOT;
        P[lane]      = klm * rn;        // kn
        P[NN + lane] = vsum * INV32;    // v (pre-divided)
        if (lane == 0) P[2 * NN] = beta;

        __syncwarp();   // reads of this buffer done before its next prefetch
    }
}

// ============================================================================
// Phase 2: the sequential scan. 64 CTAs x 128 threads; warp w owns S columns
// [8w, 8w+8), lane = row. Params streamed from g_param via cp.async ring.
// ============================================================================
__global__ __launch_bounds__(128, 1)
void e86_phase2(const float* __restrict__ S0,
                float* __restrict__ out,
                int write_sfinal)
{
    __shared__ __align__(16) float pring[PDEPTH * PSLOT];
    __shared__ float rpart[2][4][NN + 1];   // +1 pad: kill bank conflicts
    __shared__ float qpart[2][4][NN + 1];

    const int tid  = threadIdx.x;
    const int w    = tid >> 5;
    const int lane = tid & 31;
    const int head = blockIdx.x;

    // S[j] = S[lane][8w+j]
    float S[8];
    {
        const float* p = S0 + (size_t)head * (NN * NN) + (size_t)lane * NN + 8 * w;
        #pragma unroll
        for (int j = 0; j < 8; j++) S[j] = p[j];
    }

    const float* psrc = g_param + (size_t)head * PSLOT;
    const size_t pstride = (size_t)NHEAD * PSLOT;
    const uint32_t spr = (uint32_t)__cvta_generic_to_shared(pring);

    // ---- prologue: 8 param groups (steps 0..7), 18 x 16B chunks each ----
    #pragma unroll
    for (int s = 0; s < PDEPTH; s++) {
        if (tid < 18) cp16(spr + (uint32_t)(s * PSLOT * 4 + tid * 16),
                           psrc + (size_t)s * pstride + tid * 4);
        cpcommit();
    }
    cpwait<6>();            // steps 0,1 retired
    __syncthreads();        // visible to all

    // params for the CURRENT step
    float kn[8], vv, beta;
    {
        const float* ps = pring;
        #pragma unroll
        for (int j = 0; j < 8; j++) kn[j] = ps[8 * w + j];
        vv   = ps[NN + lane];
        beta = ps[2 * NN];
    }

    // ---- main scan: one barrier per step ----
    for (int t = 0; t < TT; t++) {
        const int p  = t & 1;
        const int pn = p ^ 1;

        // [chain head] retrieved partial (this warp's 8 columns)
        {
            float r0 = S[0] * kn[0], r1 = S[1] * kn[1];
            float r2 = S[2] * kn[2], r3 = S[3] * kn[3];
            r0 = fmaf(S[4], kn[4], r0); r1 = fmaf(S[5], kn[5], r1);
            r2 = fmaf(S[6], kn[6], r2); r3 = fmaf(S[7], kn[7], r3);
            rpart[p][w][lane] = (r0 + r1) + (r2 + r3);
        }

        cpwait<6>();        // groups <= t+1 retired => params t+1 resident
        __syncthreads();    // BAR(t)

        // [chain] combine -> delta
        float ret = (rpart[p][0][lane] + rpart[p][1][lane])
                  + (rpart[p][2][lane] + rpart[p][3][lane]);

        // [overlap] issue param loads for step t+1 now; latency hides under tanh
        float kn2[8], vv2, beta2;
        if (t + 1 < TT) {
            const float* ps = pring + ((t + 1) & 7) * PSLOT;
            #pragma unroll
            for (int j = 0; j < 8; j++) kn2[j] = ps[8 * w + j];
            vv2   = ps[NN + lane];
            beta2 = ps[2 * NN];
        }

        // [chain] delta; tanh -> S_new
        {
            float delta = vv - ret;
            float b2 = C2 * beta, d2 = C2 * delta;
            #pragma unroll
            for (int j = 0; j < 8; j++) {
                float z = fmaf(b2, S[j], d2 * kn[j]);
                S[j] = fmaf(2.0f, rcpf(1.0f + ex2f(z)), -1.0f);
            }
        }

        // [chain tail] Sq partial for step t
        {
            float q0 = S[0] * kn[0], q1 = S[1] * kn[1];
            float q2 = S[2] * kn[2], q3 = S[3] * kn[3];
            q0 = fmaf(S[4], kn[4], q0); q1 = fmaf(S[5], kn[5], q1);
            q2 = fmaf(S[6], kn[6], q2); q3 = fmaf(S[7], kn[7], q3);
            qpart[p][w][lane] = (q0 + q1) + (q2 + q3);
        }

        // [off-chain] output for step t-1 (qpart[pn] valid since BAR(t))
        if (t >= 1 && lane < 8) {
            const int row = 8 * w + lane;
            float q = (qpart[pn][0][row] + qpart[pn][1][row])
                    + (qpart[pn][2][row] + qpart[pn][3][row]);
            float sg = rcpf(1.0f + ex2f(-L2E * q));
            out[(size_t)(t - 1) * (BB * HH * NN) + (size_t)head * NN + row] = q * q * sg;
        }

        // [off-chain] refill slot t&7 with step t+8 (last read: params t, iter t-1)
        if (tid < 18 && t + PDEPTH < TT)
            cp16(spr + (uint32_t)((t & 7) * PSLOT * 4 + tid * 16),
                 psrc + (size_t)(t + PDEPTH) * pstride + tid * 4);
        cpcommit();         // exactly one group per iteration

        // rotate params
        if (t + 1 < TT) {
            #pragma unroll
            for (int j = 0; j < 8; j++) kn[j] = kn2[j];
            vv = vv2; beta = beta2;
        }
    }

    // tail: output for step TT-1, optional S_final
    __syncthreads();
    {
        const int pl = (TT - 1) & 1;
        if (lane < 8) {
            const int row = 8 * w + lane;
            float q = (qpart[pl][0][row] + qpart[pl][1][row])
                    + (qpart[pl][2][row] + qpart[pl][3][row]);
            float sg = rcpf(1.0f + ex2f(-L2E * q));
            out[(size_t)(TT - 1) * (BB * HH * NN) + (size_t)head * NN + row] = q * q * sg;
        }
    }
    if (write_sfinal) {
        float* dst = out + (size_t)TT * (BB * HH * NN)
                   + (size_t)head * (NN * NN) + (size_t)lane * NN + 8 * w;
        #pragma unroll
        for (int j = 0; j < 8; j++) dst[j] = S[j];
    }
}

extern "C" void kernel_launch(void* const* d_in, const int* in_sizes, int n_in,
                              void* d_out, int out_size)
{
    const float* x       = (const float*)d_in[0];
    const float* S0      = (const float*)d_in[1];
    const float* scale_p = (const float*)d_in[2];
    const float* bias_p  = (const float*)d_in[3];
    float* out = (float*)d_out;

    const int out_main = TT * BB * HH * NN;              // 2,097,152
    const int out_full = out_main + BB * HH * NN * NN;   // 2,162,688
    const int write_sfinal = (out_size >= out_full) ? 1 : 0;

    e86_phase1<<<888, 128>>>(x, scale_p, bias_p);
    e86_phase2<<<NHEAD, 128>>>(S0, out, write_sfinal);
}